// round 5
// baseline (speedup 1.0000x reference)
#include <cuda_runtime.h>
#include <cstdint>

#define DIMZ 96
#define OUT_ROW 4753            // 1 + 96 + 96*97/2
#define G 4                     // rows per CTA
#define TPB 256
#define NVEC 4753               // float4 slots per CTA superblock (G*OUT_ROW/4)
#define NSEG (G * 97)           // 388 segments per superblock
#define CST 400                 // rotated-copy stride in words (mult of 4)

// slot-compacted descriptor table:
//  uniform slot: bit31=0, v[30:18], a[17:9], b[8:0]  -> out4[v] = zext[a]*zext[b..b+3]
//  crossing slot: bit31=1, v[24:12], cidx[11:0]      -> 4 pairs from g_cross[cidx]
__device__ uint32_t g_desc[NVEC];
__device__ uint4    g_cross[1024];   // per crossing slot: 4x ((a<<16)|b)

__device__ __forceinline__ void elem_ab(int l, int& a, int& b) {
    int r = l / OUT_ROW;
    int k = l - r * OUT_ROW;
    if (k < 97) { a = r * 97; b = r * 97 + k; return; }   // const/linear prefix
    int q = k - 97, i = 0, acc = 0;
    while (acc + (96 - i) <= q) { acc += 96 - i; ++i; }
    int j = i + (q - acc);
    a = r * 97 + i + 1;
    b = r * 97 + j + 1;
}

// Single-block table builder. Deterministic; runs every launch (~2us).
__global__ __launch_bounds__(512) void init_tbl_kernel() {
    __shared__ int su[512], sc[512], s_nu[1];
    const int t = threadIdx.x;

    int E = 0, L = 0, a = 0, u = 0, cf = 0;
    if (t < NSEG) {
        int r = t / 97, s = t - r * 97;
        int Srow = 97 * s - (s * (s - 1)) / 2;  // start of segment s within a row
        E = r * OUT_ROW + Srow;                 // global start in superblock
        L = 97 - s;
        a = r * 97 + s;
        int vlo = (E + 3) >> 2, vhi = (E + L) >> 2;
        u = (vhi > vlo) ? (vhi - vlo) : 0;
        int End = E + L;
        if (End & 3) {
            int Lnext = (s < 96) ? (96 - s) : 97;        // next segment length
            int End2 = End + Lnext;                      // t==387 never crosses
            if ((End2 >> 2) > (End >> 2)) cf = 1;        // this seg owns the crossing v
        }
    }
    su[t] = u; sc[t] = cf;
    __syncthreads();

    // Hillis-Steele inclusive scans over 512
    for (int d = 1; d < 512; d <<= 1) {
        int xu = su[t], xc = sc[t];
        if (t >= d) { xu += su[t - d]; xc += sc[t - d]; }
        __syncthreads();
        su[t] = xu; sc[t] = xc;
        __syncthreads();
    }
    if (t == 0) s_nu[0] = su[511];   // total uniform slots
    __syncthreads();
    const int NU = s_nu[0];

    if (t < NSEG) {
        int Ubase = su[t] - u;       // exclusive prefix
        int vlo = (E + 3) >> 2;
        for (int m = 0; m < u; m++) {
            int v = vlo + m;
            int b = a + (4 * v - E);
            g_desc[Ubase + m] = ((uint32_t)v << 18) | ((uint32_t)a << 9) | (uint32_t)b;
        }
        if (cf) {
            int cidx = sc[t] - 1;    // exclusive prefix of crossing flags
            int v = (E + L) >> 2;
            uint4 pp;
            int aa, bb;
            elem_ab(4 * v + 0, aa, bb); pp.x = ((uint32_t)aa << 16) | (uint32_t)bb;
            elem_ab(4 * v + 1, aa, bb); pp.y = ((uint32_t)aa << 16) | (uint32_t)bb;
            elem_ab(4 * v + 2, aa, bb); pp.z = ((uint32_t)aa << 16) | (uint32_t)bb;
            elem_ab(4 * v + 3, aa, bb); pp.w = ((uint32_t)aa << 16) | (uint32_t)bb;
            g_cross[cidx] = pp;
            g_desc[NU + cidx] = 0x80000000u | ((uint32_t)v << 12) | (uint32_t)cidx;
        }
    }
}

__global__ __launch_bounds__(TPB) void poly_kernel(const float* __restrict__ z,
                                                   float* __restrict__ out) {
    // 4 rotated copies of zext (388 entries + pad): zsh[c*CST + x] = zext(x + c).
    // zext(y): y%97==0 -> 1.0 else z_row[y%97 - 1], rows concatenated.
    __shared__ float zsh[4 * CST];

    const int tid = threadIdx.x;
    const float* zr = z + (size_t)blockIdx.x * (G * DIMZ);

    for (int w = tid; w < 4 * CST; w += TPB) {
        int c = w / CST;
        int x = w - c * CST;
        int y = x + c;
        float val = 1.0f;
        if (y < NSEG) {
            int row = y / 97, pos = y - row * 97;
            if (pos > 0) val = zr[row * DIMZ + pos - 1];
        }
        zsh[w] = val;
    }
    __syncthreads();

    float4* o4 = (float4*)(out + (size_t)blockIdx.x * (G * OUT_ROW));

    for (int slot = tid; slot < NVEC; slot += TPB) {
        const uint32_t d = __ldg(&g_desc[slot]);
        if (!(d & 0x80000000u)) {
            const int v = d >> 18;
            const int a = (d >> 9) & 511;
            const int b = d & 511;
            const int c = b & 3;
            const float4 zj = *(const float4*)&zsh[c * CST + (b - c)];
            const float  zi = zsh[a];
            float4 res;
            res.x = zi * zj.x;
            res.y = zi * zj.y;
            res.z = zi * zj.z;
            res.w = zi * zj.w;
            o4[v] = res;
        } else {
            const int idx = d & 0xFFF;
            const int v = (d >> 12) & 0x1FFF;
            const uint4 pp = __ldg(&g_cross[idx]);
            float4 res;
            res.x = zsh[pp.x >> 16] * zsh[pp.x & 0xFFFFu];
            res.y = zsh[pp.y >> 16] * zsh[pp.y & 0xFFFFu];
            res.z = zsh[pp.z >> 16] * zsh[pp.z & 0xFFFFu];
            res.w = zsh[pp.w >> 16] * zsh[pp.w & 0xFFFFu];
            o4[v] = res;
        }
    }
}

extern "C" void kernel_launch(void* const* d_in, const int* in_sizes, int n_in,
                              void* d_out, int out_size) {
    const float* z = (const float*)d_in[0];
    float* out = (float*)d_out;
    const int B = in_sizes[0] / DIMZ;   // 32768, divisible by G=4

    init_tbl_kernel<<<1, 512>>>();
    poly_kernel<<<B / G, TPB>>>(z, out);
}

// round 6
// speedup vs baseline: 1.0679x; 1.0679x over previous
#include <cuda_runtime.h>
#include <cstdint>

#define DIMZ 96
#define OUT_ROW 4753            // 1 + 96 + 96*97/2
#define G 4                     // rows per CTA
#define TPB 256
#define NVEC 4753               // float4s per CTA superblock (G*OUT_ROW/4)
#define NSEG (G * 97)           // 388 zext-segments per superblock
#define CST 392                 // rotated-copy stride in words (mult of 8)
#define FLAG 0x80000000u

// Per-float4 table: bits 0..9 = b, 10..19 = a, bit 31 = crossing flag.
__device__ uint32_t g_ab[NVEC];
// Compacted crossing list: x = v | (p<<13), y = a | (b<<10).
__device__ uint2 g_cross[1024];
__device__ int   g_ncross;

// flat zext-pair of superblock-local element l
__device__ __forceinline__ void elem_ab(int l, int& a, int& b) {
    int r = l / OUT_ROW;
    int k = l - r * OUT_ROW;
    int base = r * 97;
    if (k < 97) { a = base; b = base + k; return; }
    int q = k - 97, i = 0, acc = 0;
    while (acc + (96 - i) <= q) { acc += 96 - i; ++i; }
    int j = i + (q - acc);
    a = base + i + 1;
    b = base + j + 1;
}

// per-v (a,b) + crossing flag
__global__ void init_ab_kernel() {
    int v = blockIdx.x * blockDim.x + threadIdx.x;
    if (v >= NVEC) return;
    int a0, b0, a3, b3;
    elem_ab(4 * v, a0, b0);
    elem_ab(4 * v + 3, a3, b3);
    uint32_t d = (uint32_t)b0 | ((uint32_t)a0 << 10);
    if (a3 != a0) d |= FLAG;
    g_ab[v] = d;
}

// single-block scan: compacted crossing list in deterministic segment order
__global__ __launch_bounds__(512) void init_cross_kernel() {
    __shared__ int sc[512];
    const int t = threadIdx.x;

    int E = 0, L = 0, cf = 0;
    if (t < NSEG) {
        int r = t / 97, s = t - r * 97;
        int Srow = 97 * s - (s * (s - 1)) / 2;
        E = r * OUT_ROW + Srow;
        L = 97 - s;
        int End = E + L;
        if (End & 3) {
            int Lnext = (s < 96) ? (96 - s) : 97;
            if (((End + Lnext) >> 2) > (End >> 2)) cf = 1;  // this seg owns v
        }
    }
    sc[t] = cf;
    __syncthreads();
    for (int d = 1; d < 512; d <<= 1) {
        int x = sc[t];
        if (t >= d) x += sc[t - d];
        __syncthreads();
        sc[t] = x;
        __syncthreads();
    }
    if (t == 0) g_ncross = sc[511];

    if (t < NSEG && cf) {
        int cidx = sc[t] - 1;
        int v = (E + L) >> 2;
        int a[4], b[4];
        #pragma unroll
        for (int e = 0; e < 4; e++) elem_ab(4 * v + e, a[e], b[e]);
        uint32_t p = 0;
        if (a[1] != a[0]) p |= 1u;
        if (a[2] != a[1]) p |= 2u;
        if (a[3] != a[2]) p |= 4u;
        uint2 ent;
        ent.x = (uint32_t)v | (p << 13);
        ent.y = (uint32_t)a[0] | ((uint32_t)b[0] << 10);
        g_cross[cidx] = ent;
    }
}

__global__ __launch_bounds__(TPB) void poly_kernel(const float* __restrict__ z,
                                                   float* __restrict__ out) {
    // 4 rotated copies of zext: zsh[c*CST + x] = zext(x + c), zero-padded.
    // zext(y): y%97==0 -> 1.0, else z_row[y%97 - 1], rows concatenated.
    __shared__ float zsh[4 * CST];

    const int tid = threadIdx.x;
    const float* zr = z + (size_t)blockIdx.x * (G * DIMZ);

    for (int w = tid; w < 4 * CST; w += TPB) {
        int c = w / CST;
        int x = w - c * CST;
        int y = x + c;
        float val = 0.0f;
        if (y < NSEG) {
            int row = y / 97, pos = y - row * 97;
            val = (pos == 0) ? 1.0f : zr[row * DIMZ + pos - 1];
        }
        zsh[w] = val;
    }
    __syncthreads();

    float4* o4 = (float4*)(out + (size_t)blockIdx.x * (G * OUT_ROW));

    // ---- fast loop: branch-free, store address = induction var ----
    #pragma unroll 4
    for (int v = tid; v < NVEC; v += TPB) {
        const uint32_t d = __ldg(&g_ab[v]);
        const int b = d & 1023;
        const int a = (d >> 10) & 1023;
        const int c = b & 3;
        const float4 zj = *(const float4*)&zsh[c * CST + (b - c)];
        const float  zi = zsh[a];
        float4 res;
        res.x = zi * zj.x;
        res.y = zi * zj.y;
        res.z = zi * zj.z;
        res.w = zi * zj.w;
        if (!(d & FLAG)) o4[v] = res;     // predicated store
    }

    // ---- fixup: the ~291 segment-crossing float4s ----
    const int nc = g_ncross;
    for (int s = tid; s < nc; s += TPB) {
        const uint2 e = __ldg(&g_cross[s]);
        const int v = e.x & 0x1FFF;
        const uint32_t p = e.x >> 13;
        int a = e.y & 1023;
        int b = (e.y >> 10) & 1023;
        float4 res;
        res.x = zsh[a] * zsh[b];
        a += (p & 1u);        b = (p & 1u) ? a : (b + 1);
        res.y = zsh[a] * zsh[b];
        a += ((p >> 1) & 1u); b = ((p >> 1) & 1u) ? a : (b + 1);
        res.z = zsh[a] * zsh[b];
        a += ((p >> 2) & 1u); b = ((p >> 2) & 1u) ? a : (b + 1);
        res.w = zsh[a] * zsh[b];
        o4[v] = res;
    }
}

extern "C" void kernel_launch(void* const* d_in, const int* in_sizes, int n_in,
                              void* d_out, int out_size) {
    const float* z = (const float*)d_in[0];
    float* out = (float*)d_out;
    const int B = in_sizes[0] / DIMZ;   // 32768, divisible by G=4

    init_ab_kernel<<<(NVEC + 255) / 256, 256>>>();
    init_cross_kernel<<<1, 512>>>();
    poly_kernel<<<B / G, TPB>>>(z, out);
}

// round 7
// speedup vs baseline: 1.6762x; 1.5695x over previous
#include <cuda_runtime.h>
#include <cstdint>

#define DIMZ 96
#define OUT_ROW 4753            // 1 + 96 + 96*97/2
#define G 4                     // rows per CTA
#define TPB 256
#define NVEC 4753               // float4s per CTA superblock (G*OUT_ROW/4)
#define NSEG (G * 97)           // 388 zext-segments per superblock
#define CST 392                 // rotated-copy stride in words (mult of 8)

// Per-float4 descriptor: bits 0..9 = b, bits 10..19 = a.
// Meaning: out4[v] = zext[a] * zext[b..b+3] (valid for non-crossing slots;
// crossing slots get garbage here and are overwritten by the fixup loop).
__device__ uint32_t g_ab[NVEC];
// Compacted crossing list: x = v | (p<<13), y = a | (b<<10).
__device__ uint2 g_cross[1024];
__device__ int   g_ncross;

// flat zext-pair of superblock-local element l
__device__ __forceinline__ void elem_ab(int l, int& a, int& b) {
    int r = l / OUT_ROW;
    int k = l - r * OUT_ROW;
    int base = r * 97;
    if (k < 97) { a = base; b = base + k; return; }
    int q = k - 97, i = 0, acc = 0;
    while (acc + (96 - i) <= q) { acc += 96 - i; ++i; }
    int j = i + (q - acc);
    a = base + i + 1;
    b = base + j + 1;
}

__global__ void init_ab_kernel() {
    int v = blockIdx.x * blockDim.x + threadIdx.x;
    if (v >= NVEC) return;
    int a0, b0;
    elem_ab(4 * v, a0, b0);
    g_ab[v] = (uint32_t)b0 | ((uint32_t)a0 << 10);
}

// single-block scan: compacted crossing list in deterministic segment order
__global__ __launch_bounds__(512) void init_cross_kernel() {
    __shared__ int sc[512];
    const int t = threadIdx.x;

    int E = 0, L = 0, cf = 0;
    if (t < NSEG) {
        int r = t / 97, s = t - r * 97;
        int Srow = 97 * s - (s * (s - 1)) / 2;
        E = r * OUT_ROW + Srow;
        L = 97 - s;
        int End = E + L;
        if (End & 3) {
            int Lnext = (s < 96) ? (96 - s) : 97;
            if (((End + Lnext) >> 2) > (End >> 2)) cf = 1;  // this seg owns v
        }
    }
    sc[t] = cf;
    __syncthreads();
    for (int d = 1; d < 512; d <<= 1) {
        int x = sc[t];
        if (t >= d) x += sc[t - d];
        __syncthreads();
        sc[t] = x;
        __syncthreads();
    }
    if (t == 0) g_ncross = sc[511];

    if (t < NSEG && cf) {
        int cidx = sc[t] - 1;
        int v = (E + L) >> 2;
        int a[4], b[4];
        #pragma unroll
        for (int e = 0; e < 4; e++) elem_ab(4 * v + e, a[e], b[e]);
        uint32_t p = 0;
        if (a[1] != a[0]) p |= 1u;
        if (a[2] != a[1]) p |= 2u;
        if (a[3] != a[2]) p |= 4u;
        uint2 ent;
        ent.x = (uint32_t)v | (p << 13);
        ent.y = (uint32_t)a[0] | ((uint32_t)b[0] << 10);
        g_cross[cidx] = ent;
    }
}

__global__ __launch_bounds__(TPB) void poly_kernel(const float* __restrict__ z,
                                                   float* __restrict__ out) {
    // 4 rotated copies of zext: zsh[c*CST + x] = zext(x + c), zero-padded.
    // zext(y): y%97==0 -> 1.0, else z_row[y%97 - 1], rows concatenated.
    __shared__ float zsh[4 * CST];

    const int tid = threadIdx.x;
    const float* zr = z + (size_t)blockIdx.x * (G * DIMZ);

    for (int w = tid; w < 4 * CST; w += TPB) {
        int c = w / CST;
        int x = w - c * CST;
        int y = x + c;
        float val = 0.0f;
        if (y < NSEG) {
            int row = y / 97, pos = y - row * 97;
            val = (pos == 0) ? 1.0f : zr[row * DIMZ + pos - 1];
        }
        zsh[w] = val;
    }
    __syncthreads();

    float4* o4 = (float4*)(out + (size_t)blockIdx.x * (G * OUT_ROW));

    // ---- main loop: completely branch-free; crossing slots get garbage ----
    #pragma unroll 4
    for (int v = tid; v < NVEC; v += TPB) {
        const uint32_t d = __ldg(&g_ab[v]);
        const int b = d & 1023;
        const int a = (d >> 10) & 1023;
        const int c = b & 3;
        const float4 zj = *(const float4*)&zsh[c * CST + (b - c)];
        const float  zi = zsh[a];
        float4 res;
        res.x = zi * zj.x;
        res.y = zi * zj.y;
        res.z = zi * zj.z;
        res.w = zi * zj.w;
        o4[v] = res;                       // unconditional store
    }

    // Barrier orders all main-loop stores (all warps) before fixup stores,
    // so the fixup values below are the final ones at crossing slots.
    __syncthreads();

    // ---- fixup: overwrite the ~291 segment-crossing float4s ----
    const int nc = g_ncross;
    for (int s = tid; s < nc; s += TPB) {
        const uint2 e = __ldg(&g_cross[s]);
        const int v = e.x & 0x1FFF;
        const uint32_t p = e.x >> 13;
        int a = e.y & 1023;
        int b = (e.y >> 10) & 1023;
        float4 res;
        res.x = zsh[a] * zsh[b];
        a += (p & 1u);        b = (p & 1u) ? a : (b + 1);
        res.y = zsh[a] * zsh[b];
        a += ((p >> 1) & 1u); b = ((p >> 1) & 1u) ? a : (b + 1);
        res.z = zsh[a] * zsh[b];
        a += ((p >> 2) & 1u); b = ((p >> 2) & 1u) ? a : (b + 1);
        res.w = zsh[a] * zsh[b];
        o4[v] = res;
    }
}

extern "C" void kernel_launch(void* const* d_in, const int* in_sizes, int n_in,
                              void* d_out, int out_size) {
    const float* z = (const float*)d_in[0];
    float* out = (float*)d_out;
    const int B = in_sizes[0] / DIMZ;   // 32768, divisible by G=4

    init_ab_kernel<<<(NVEC + 255) / 256, 256>>>();
    init_cross_kernel<<<1, 512>>>();
    poly_kernel<<<B / G, TPB>>>(z, out);
}

// round 8
// speedup vs baseline: 1.9691x; 1.1747x over previous
#include <cuda_runtime.h>
#include <cstdint>

#define DIMZ 96
#define OUT_ROW 4753            // 1 + 96 + 96*97/2
#define G 4                     // rows per CTA
#define TPB 256
#define NVEC 4753               // float4s per CTA superblock (G*OUT_ROW/4)
#define NSEG (G * 97)           // 388 zext-segments per superblock
#define CST 392                 // rotated-copy stride in words (mult of 8)

// Per-float4 descriptor: bits 0..12 = byte offset of zj LDS.128 (rotated copy
// folded in), bits 13..23 = byte offset of zi. Crossing slots hold garbage and
// are overwritten by the fixup loop.
__device__ uint32_t g_ab[NVEC];
// Compacted crossing list: x = v | (p<<13), y = a | (b<<10)  (word indices).
__device__ uint2 g_cross[1024];
__device__ int   g_ncross;

// flat zext-pair of superblock-local element l (closed form + integer fixup)
__device__ __forceinline__ void elem_ab(int l, int& a, int& b) {
    int r = l / OUT_ROW;
    int k = l - r * OUT_ROW;
    int base = r * 97;
    if (k < 97) { a = base; b = base + k; return; }
    int q = k - 97;
    int i = (int)((193.0f - sqrtf((float)(37249 - 8 * q))) * 0.5f);
    if (i < 0) i = 0;
    while (i > 0 && (i * 96 - (i * (i - 1)) / 2) > q) --i;
    while (((i + 1) * 96 - ((i + 1) * i) / 2) <= q) ++i;
    int acc = i * 96 - (i * (i - 1)) / 2;
    int j = i + (q - acc);
    a = base + i + 1;
    b = base + j + 1;
}

// Single merged init: all blocks fill g_ab; block 0 also builds the crossing list.
__global__ __launch_bounds__(512) void init_kernel() {
    const int t = threadIdx.x;
    const int v = blockIdx.x * 512 + t;

    if (v < NVEC) {
        int a0, b0;
        elem_ab(4 * v, a0, b0);
        int c = b0 & 3;
        uint32_t zjb = (uint32_t)(4 * (c * CST + (b0 - c)));  // <= 6240, 13 bits
        uint32_t ab  = (uint32_t)(4 * a0);                    // <= 1548, 11 bits
        g_ab[v] = zjb | (ab << 13);
    }

    if (blockIdx.x != 0) return;

    __shared__ int sc[512];
    int E = 0, L = 0, cf = 0;
    if (t < NSEG) {
        int r = t / 97, s = t - r * 97;
        int Srow = 97 * s - (s * (s - 1)) / 2;
        E = r * OUT_ROW + Srow;
        L = 97 - s;
        int End = E + L;
        if (End & 3) {
            int Lnext = (s < 96) ? (96 - s) : 97;
            if (((End + Lnext) >> 2) > (End >> 2)) cf = 1;  // this seg owns v
        }
    }
    sc[t] = cf;
    __syncthreads();
    for (int d = 1; d < 512; d <<= 1) {
        int x = sc[t];
        if (t >= d) x += sc[t - d];
        __syncthreads();
        sc[t] = x;
        __syncthreads();
    }
    if (t == 0) g_ncross = sc[511];

    if (t < NSEG && cf) {
        int cidx = sc[t] - 1;
        int vx = (E + L) >> 2;
        int a[4], b[4];
        #pragma unroll
        for (int e = 0; e < 4; e++) elem_ab(4 * vx + e, a[e], b[e]);
        uint32_t p = 0;
        if (a[1] != a[0]) p |= 1u;
        if (a[2] != a[1]) p |= 2u;
        if (a[3] != a[2]) p |= 4u;
        uint2 ent;
        ent.x = (uint32_t)vx | (p << 13);
        ent.y = (uint32_t)a[0] | ((uint32_t)b[0] << 10);
        g_cross[cidx] = ent;
    }
}

__global__ __launch_bounds__(TPB) void poly_kernel(const float* __restrict__ z,
                                                   float* __restrict__ out) {
    // 4 rotated copies of zext: zsh[c*CST + x] = zext(x + c), zero-padded.
    // zext(y): y%97==0 -> 1.0, else z_row[y%97 - 1], rows concatenated.
    __shared__ float zsh[4 * CST];

    const int tid = threadIdx.x;
    const float* zr = z + (size_t)blockIdx.x * (G * DIMZ);

    for (int w = tid; w < 4 * CST; w += TPB) {
        int c = w / CST;
        int x = w - c * CST;
        int y = x + c;
        float val = 0.0f;
        if (y < NSEG) {
            int row = y / 97, pos = y - row * 97;
            val = (pos == 0) ? 1.0f : zr[row * DIMZ + pos - 1];
        }
        zsh[w] = val;
    }
    __syncthreads();

    float4* o4 = (float4*)(out + (size_t)blockIdx.x * (G * OUT_ROW));
    const char* zb8 = (const char*)zsh;

    // ---- main loop: branch-free; crossing slots get garbage, fixed below ----
    #pragma unroll 4
    for (int v = tid; v < NVEC; v += TPB) {
        const uint32_t d = __ldg(&g_ab[v]);
        const float4 zj = *(const float4*)(zb8 + (d & 0x1FFFu));
        const float  zi = *(const float*)(zb8 + (d >> 13));
        float4 res;
        res.x = zi * zj.x;
        res.y = zi * zj.y;
        res.z = zi * zj.z;
        res.w = zi * zj.w;
        __stcs(&o4[v], res);               // streaming, unconditional
    }

    // Barrier orders all main-loop stores before the fixup overwrites.
    __syncthreads();

    // ---- fixup: overwrite the ~291 segment-crossing float4s ----
    const int nc = g_ncross;
    for (int s = tid; s < nc; s += TPB) {
        const uint2 e = __ldg(&g_cross[s]);
        const int v = e.x & 0x1FFF;
        const uint32_t p = e.x >> 13;
        int a = e.y & 1023;
        int b = (e.y >> 10) & 1023;
        float4 res;
        res.x = zsh[a] * zsh[b];
        a += (p & 1u);        b = (p & 1u) ? a : (b + 1);
        res.y = zsh[a] * zsh[b];
        a += ((p >> 1) & 1u); b = ((p >> 1) & 1u) ? a : (b + 1);
        res.z = zsh[a] * zsh[b];
        a += ((p >> 2) & 1u); b = ((p >> 2) & 1u) ? a : (b + 1);
        res.w = zsh[a] * zsh[b];
        __stcs(&o4[v], res);
    }
}

extern "C" void kernel_launch(void* const* d_in, const int* in_sizes, int n_in,
                              void* d_out, int out_size) {
    const float* z = (const float*)d_in[0];
    float* out = (float*)d_out;
    const int B = in_sizes[0] / DIMZ;   // 32768, divisible by G=4

    init_kernel<<<10, 512>>>();
    poly_kernel<<<B / G, TPB>>>(z, out);
}